// round 8
// baseline (speedup 1.0000x reference)
#include <cuda_runtime.h>
#include <cuda_bf16.h>
#include <cstdint>

// ============================================================================
// CompetitiveLayer: C = outer(AF_, BF_) * K after 20 fixed-point iterations of
//   AF = AT / (BF @ K^T + 1);  BF = BTb / (AF @ K + 1)
// with K = exp(k), BT = exp(bt).
//
// Design (stable across R1-R7 broker outages; never yet benched):
//  - 2 rows per thread packed into f32x2 lanes; all matvec FMAs issued as
//    fma.rn.f32x2 (FFMA2 — ptxas never auto-emits it from C++; PTX-only).
//  - Packed values are u64 with "l" constraints (.b64 regs), matching the
//    proven ptx_helpers.cuh f32x2 macros.
//  - K lane-duplicated in 128 regs; ~210 live regs worst case after fusing
//    denominator->rcp->mul (no d[8]/e[8] arrays); 8 warps/SM.
//  - rcp.approx.f32 on MUFU (~74k cyc budget overlaps the ~75k FMA pipe).
//  - Outer 20-loop rolled: ~2.3KB body fits L0 I$.
//  - Epilogue reuses iter-20's v as BF_ (reference computes BF_ from solve-AF,
//    which is exactly what produced v in the last half-step).
//  - Streaming st.global.cs.v4 for the 134MB write-once output (> L2).
// ============================================================================

typedef unsigned long long u64;

#define DFMA2(r, a, b, c) asm("fma.rn.f32x2 %0, %1, %2, %3;" : "=l"(r) : "l"(a), "l"(b), "l"(c))
#define DMUL2(r, a, b)    asm("mul.rn.f32x2 %0, %1, %2;"     : "=l"(r) : "l"(a), "l"(b))

__device__ __forceinline__ u64 pack2(float lo, float hi) {
    u64 r;
    asm("mov.b64 %0, {%1, %2};" : "=l"(r) : "f"(lo), "f"(hi));
    return r;
}
__device__ __forceinline__ void unpack2(u64 x, float& lo, float& hi) {
    asm("mov.b64 {%0, %1}, %2;" : "=f"(lo), "=f"(hi) : "l"(x));
}
__device__ __forceinline__ float rcpf(float x) {
    float r;
    asm("rcp.approx.f32 %0, %1;" : "=f"(r) : "f"(x));
    return r;
}
__device__ __forceinline__ u64 rcp2(u64 x) {
    float lo, hi;
    unpack2(x, lo, hi);
    return pack2(rcpf(lo), rcpf(hi));
}
__device__ __forceinline__ void stcs4(float* p, float x, float y, float z, float w) {
    asm volatile("st.global.cs.v4.f32 [%0], {%1, %2, %3, %4};"
                 :: "l"(p), "f"(x), "f"(y), "f"(z), "f"(w) : "memory");
}

static constexpr int N_ITERS = 20;
static constexpr int TPB     = 64;   // threads per block; each thread owns 2 rows

__global__ __launch_bounds__(TPB)
void competitive_kernel(const float* __restrict__ AT,
                        const float* __restrict__ k_raw,
                        const float* __restrict__ bt_raw,
                        float* __restrict__ C,
                        int B)
{
    __shared__ float Ks[64];
    __shared__ float BTs[8];

    const int tid = threadIdx.x;
    if (tid < 64) Ks[tid]  = expf(k_raw[tid]);
    if (tid < 8)  BTs[tid] = expf(bt_raw[tid]);
    __syncthreads();

    const long long r0 = ((long long)blockIdx.x * TPB + tid) * 2;
    if (r0 >= B) return;
    const bool has2 = (r0 + 1 < B);
    const long long r1 = has2 ? (r0 + 1) : r0;

    // K duplicated across both f32x2 lanes (both rows share K).
    u64 Kd[64];
#pragma unroll
    for (int m = 0; m < 64; m++) Kd[m] = pack2(Ks[m], Ks[m]);

    u64 BTd[8];
#pragma unroll
    for (int j = 0; j < 8; j++) BTd[j] = pack2(BTs[j], BTs[j]);

    // Load AT rows r0 (lo lane) and r1 (hi lane).
    u64 at[8];
    {
        const float4* p0 = reinterpret_cast<const float4*>(AT + r0 * 8);
        const float4* p1 = reinterpret_cast<const float4*>(AT + r1 * 8);
        float4 a0 = p0[0], a1 = p0[1];
        float4 b0 = p1[0], b1 = p1[1];
        at[0] = pack2(a0.x, b0.x); at[1] = pack2(a0.y, b0.y);
        at[2] = pack2(a0.z, b0.z); at[3] = pack2(a0.w, b0.w);
        at[4] = pack2(a1.x, b1.x); at[5] = pack2(a1.y, b1.y);
        at[6] = pack2(a1.z, b1.z); at[7] = pack2(a1.w, b1.w);
    }

    const u64 ONE2 = pack2(1.0f, 1.0f);

    // Fixed point state: u = AF (packed), v = BF (packed). BF0 = BT broadcast.
    u64 u[8], v[8];
#pragma unroll
    for (int j = 0; j < 8; j++) v[j] = BTd[j];
#pragma unroll
    for (int i = 0; i < 8; i++) u[i] = at[i];

    // 20 iterations, outer loop rolled (L0 I$). Denominator -> rcp -> mul
    // fused per i/j to cap live registers; the 8 per-index chains stay
    // independent so ptxas overlaps MUFU latency across them.
#pragma unroll 1
    for (int it = 0; it < N_ITERS; it++) {
        // AF half: u_i = at_i * rcp(1 + sum_j K[i][j] * v_j)
#pragma unroll
        for (int i = 0; i < 8; i++) {
            u64 acc = ONE2;
#pragma unroll
            for (int j = 0; j < 8; j++) DFMA2(acc, Kd[i * 8 + j], v[j], acc);
            u64 r = rcp2(acc);
            DMUL2(u[i], at[i], r);
        }
        // BF half: v_j = BT_j * rcp(1 + sum_i K[i][j] * u_i)
#pragma unroll
        for (int j = 0; j < 8; j++) {
            u64 acc = ONE2;
#pragma unroll
            for (int i = 0; i < 8; i++) DFMA2(acc, Kd[i * 8 + j], u[i], acc);
            u64 s = rcp2(acc);
            DMUL2(v[j], BTd[j], s);
        }
    }

    // Final correction:
    //   AF_ = AT / (BF20 @ K^T + 1)   -> a_i below
    //   BF_ = BTb / (AF20 @ K + 1)    == v from iteration 20 (from u20)
    u64 a[8];
#pragma unroll
    for (int i = 0; i < 8; i++) {
        u64 acc = ONE2;
#pragma unroll
        for (int j = 0; j < 8; j++) DFMA2(acc, Kd[i * 8 + j], v[j], acc);
        u64 r = rcp2(acc);
        DMUL2(a[i], at[i], r);
    }

    // C[b][i][j] = a_i * v_j * K[i][j]; store row-pair with streaming stores.
    float* o0 = C + r0 * 64;
    float* o1 = C + r1 * 64;
#pragma unroll
    for (int i = 0; i < 8; i++) {
        float lo[8], hi[8];
#pragma unroll
        for (int j = 0; j < 8; j++) {
            u64 t, c;
            DMUL2(t, a[i], v[j]);
            DMUL2(c, t, Kd[i * 8 + j]);
            unpack2(c, lo[j], hi[j]);
        }
        stcs4(o0 + i * 8,     lo[0], lo[1], lo[2], lo[3]);
        stcs4(o0 + i * 8 + 4, lo[4], lo[5], lo[6], lo[7]);
        if (has2) {
            stcs4(o1 + i * 8,     hi[0], hi[1], hi[2], hi[3]);
            stcs4(o1 + i * 8 + 4, hi[4], hi[5], hi[6], hi[7]);
        }
    }
}

extern "C" void kernel_launch(void* const* d_in, const int* in_sizes, int n_in,
                              void* d_out, int out_size)
{
    const float* AT = (const float*)d_in[0];   // [B, 8]
    const float* k  = (const float*)d_in[1];   // [8, 8]
    const float* bt = (const float*)d_in[2];   // [1, 8]
    float* C = (float*)d_out;                  // [B, 8, 8]

    const int B = in_sizes[0] / 8;
    const int rows_per_block = TPB * 2;
    const int nblocks = (B + rows_per_block - 1) / rows_per_block;

    competitive_kernel<<<nblocks, TPB>>>(AT, k, bt, C, B);
}